// round 4
// baseline (speedup 1.0000x reference)
#include <cuda_runtime.h>
#include <cstdint>

#define B_ 16
#define T_ 1024
#define D_ 1024
#define M_ (B_ * T_)            // 16384
#define NELEM (B_ * T_ * D_)    // 16777216

// ---------------------------------------------------------------------------
// Scratch (static device globals)
// ---------------------------------------------------------------------------
__device__ float g_xt[NELEM];           // tanh(0.5*x)
__device__ float g_ic[NELEM];           // tanh(xt @ W^T)
__device__ unsigned g_spk[NELEM / 32];  // spike bits: [(b*32 + t/32)*1024 + d], bit t%32

// ---------------------------------------------------------------------------
// Helpers
// ---------------------------------------------------------------------------
__device__ __forceinline__ uint32_t smem_u32(const void* p) {
    uint32_t a;
    asm("{ .reg .u64 t; cvta.to.shared.u64 t, %1; cvt.u32.u64 %0, t; }" : "=r"(a) : "l"(p));
    return a;
}
__device__ __forceinline__ float to_tf32(float a) {
    float r;
    asm("cvt.rna.tf32.f32 %0, %1;" : "=f"(r) : "f"(a));
    return r;
}
__device__ __forceinline__ void split_tf32(float v, uint32_t& hi, uint32_t& lo) {
    float h = to_tf32(v);
    float l = to_tf32(v - h);
    hi = __float_as_uint(h);
    lo = __float_as_uint(l);
}
__device__ __forceinline__ void cpa16(uint32_t dst, const float* src) {
    asm volatile("cp.async.cg.shared.global [%0], [%1], 16;" :: "r"(dst), "l"(src));
}
#define CP_COMMIT() asm volatile("cp.async.commit_group;" ::: "memory")
#define CP_WAIT(n)  asm volatile("cp.async.wait_group %0;" :: "n"(n) : "memory")

// m16n8k8 row.col f32.tf32 MMA (sm_80+, family-portable)
__device__ __forceinline__ void mma1688(float* c, uint32_t a0, uint32_t a1,
                                        uint32_t a2, uint32_t a3,
                                        uint32_t b0, uint32_t b1) {
    asm volatile(
        "mma.sync.aligned.m16n8k8.row.col.f32.tf32.tf32.f32 "
        "{%0,%1,%2,%3}, {%4,%5,%6,%7}, {%8,%9}, {%0,%1,%2,%3};"
        : "+f"(c[0]), "+f"(c[1]), "+f"(c[2]), "+f"(c[3])
        : "r"(a0), "r"(a1), "r"(a2), "r"(a3), "r"(b0), "r"(b1));
}

// ---------------------------------------------------------------------------
// Kernel 1: xt = tanh(0.5*x)
// ---------------------------------------------------------------------------
__global__ void prep_x_kernel(const float* __restrict__ x) {
    int i = blockIdx.x * blockDim.x + threadIdx.x;  // over NELEM/4
    float4 v = ((const float4*)x)[i];
    float4 t;
    t.x = tanhf(0.5f * v.x); t.y = tanhf(0.5f * v.y);
    t.z = tanhf(0.5f * v.z); t.w = tanhf(0.5f * v.w);
    ((float4*)g_xt)[i] = t;
}

// ---------------------------------------------------------------------------
// Kernel 2: ic = tanh(xt @ W^T) via mma.sync tf32 x3 (fp32-equivalent).
// CTA 128x128, BK=16, 8 warps (warp tile 64x32), cp.async double buffer.
// grid = (8 n-tiles, 128 m-tiles), 256 threads.
// ---------------------------------------------------------------------------
#define BK 16
#define LDP 20           // padded row stride in floats (conflict-free)
#define NKT (D_ / BK)    // 64

__global__ __launch_bounds__(256, 1)
void gemm_tf32x3_kernel(const float* __restrict__ W) {
    __shared__ float sA[2][128 * LDP];
    __shared__ float sB[2][128 * LDP];

    const int tid = threadIdx.x;
    const int wid = tid >> 5;
    const int lid = tid & 31;
    const int grp = lid >> 2;       // 0..7
    const int tig = lid & 3;        // 0..3
    const int warp_m = (wid & 1) * 64;
    const int warp_n = (wid >> 1) * 32;
    const int m0 = blockIdx.y * 128;
    const int n0 = blockIdx.x * 128;

    float acc[4][4][4];
#pragma unroll
    for (int i = 0; i < 4; i++)
#pragma unroll
        for (int j = 0; j < 4; j++)
#pragma unroll
            for (int q = 0; q < 4; q++) acc[i][j][q] = 0.0f;

    // stage loader: 512 16B chunks for A, 512 for B; 256 threads x 2 each
    auto load_stage = [&](int s, int kt) {
        const int k0 = kt * BK;
        const uint32_t aBase = smem_u32(&sA[s][0]);
        const uint32_t bBase = smem_u32(&sB[s][0]);
#pragma unroll
        for (int t = 0; t < 2; t++) {
            int c = tid + t * 256;      // 0..511
            int r = c >> 2;             // row 0..127
            int kc = (c & 3) * 4;       // k sub 0,4,8,12
            cpa16(aBase + (uint32_t)(r * LDP + kc) * 4, g_xt + (size_t)(m0 + r) * D_ + k0 + kc);
            cpa16(bBase + (uint32_t)(r * LDP + kc) * 4, W + (size_t)(n0 + r) * D_ + k0 + kc);
        }
    };

    load_stage(0, 0);
    CP_COMMIT();

    for (int kt = 0; kt < NKT; kt++) {
        const int cur = kt & 1;
        if (kt + 1 < NKT) {
            load_stage(cur ^ 1, kt + 1);
            CP_COMMIT();
            CP_WAIT(1);
        } else {
            CP_WAIT(0);
        }
        __syncthreads();

        const float* As = &sA[cur][0];
        const float* Bs = &sB[cur][0];
#pragma unroll
        for (int kk = 0; kk < BK; kk += 8) {
            // A fragments: 4 m16-tiles, hi/lo
            uint32_t Ah[4][4], Al[4][4];
#pragma unroll
            for (int mt = 0; mt < 4; mt++) {
                int rm = warp_m + mt * 16 + grp;
                float a0 = As[rm * LDP + kk + tig];
                float a1 = As[(rm + 8) * LDP + kk + tig];
                float a2 = As[rm * LDP + kk + tig + 4];
                float a3 = As[(rm + 8) * LDP + kk + tig + 4];
                split_tf32(a0, Ah[mt][0], Al[mt][0]);
                split_tf32(a1, Ah[mt][1], Al[mt][1]);
                split_tf32(a2, Ah[mt][2], Al[mt][2]);
                split_tf32(a3, Ah[mt][3], Al[mt][3]);
            }
            // B fragments: 4 n8-tiles, hi/lo
            uint32_t Bh[4][2], Bl[4][2];
#pragma unroll
            for (int nt = 0; nt < 4; nt++) {
                int rn = warp_n + nt * 8 + grp;
                float b0 = Bs[rn * LDP + kk + tig];
                float b1 = Bs[rn * LDP + kk + tig + 4];
                split_tf32(b0, Bh[nt][0], Bl[nt][0]);
                split_tf32(b1, Bh[nt][1], Bl[nt][1]);
            }
#pragma unroll
            for (int mt = 0; mt < 4; mt++)
#pragma unroll
                for (int nt = 0; nt < 4; nt++) {
                    float* c = acc[mt][nt];
                    mma1688(c, Ah[mt][0], Ah[mt][1], Ah[mt][2], Ah[mt][3], Bh[nt][0], Bh[nt][1]);
                    mma1688(c, Ah[mt][0], Ah[mt][1], Ah[mt][2], Ah[mt][3], Bl[nt][0], Bl[nt][1]);
                    mma1688(c, Al[mt][0], Al[mt][1], Al[mt][2], Al[mt][3], Bh[nt][0], Bh[nt][1]);
                }
        }
        __syncthreads();
    }

    // epilogue: c0=C[g][2t], c1=C[g][2t+1], c2=C[g+8][2t], c3=C[g+8][2t+1]
#pragma unroll
    for (int mt = 0; mt < 4; mt++) {
        int rm = m0 + warp_m + mt * 16 + grp;
#pragma unroll
        for (int nt = 0; nt < 4; nt++) {
            int cn = n0 + warp_n + nt * 8 + tig * 2;
            float2 v0, v1;
            v0.x = tanhf(acc[mt][nt][0]);
            v0.y = tanhf(acc[mt][nt][1]);
            v1.x = tanhf(acc[mt][nt][2]);
            v1.y = tanhf(acc[mt][nt][3]);
            *(float2*)(g_ic + (size_t)rm * D_ + cn) = v0;
            *(float2*)(g_ic + (size_t)(rm + 8) * D_ + cn) = v1;
        }
    }
}

// ---------------------------------------------------------------------------
// Kernel 3: LIF scan -> packed spike bits. One thread per (b,d) chain.
// ---------------------------------------------------------------------------
__global__ __launch_bounds__(128)
void lif_scan_kernel(const float* __restrict__ noise) {
    const int j = blockIdx.x * blockDim.x + threadIdx.x;  // 0..16383
    const int b = j >> 10;
    const int d = j & 1023;
    const size_t base = (size_t)b * T_ * D_ + d;
    const float* icp = g_ic + base;
    const float* nzp = noise + base;

    float mem = 0.0f;
    for (int tw = 0; tw < 32; tw++) {
        float icv[32], nzv[32];
#pragma unroll
        for (int u = 0; u < 32; u++) {
            size_t idx = (size_t)(tw * 32 + u) * D_;
            icv[u] = icp[idx];
            nzv[u] = nzp[idx];
        }
        unsigned mask = 0;
#pragma unroll
        for (int u = 0; u < 32; u++) {
            mem = 0.95f * mem + icv[u] + nzv[u] * 7.5e-4f + 1e-6f;
            bool s = (mem >= 0.15f);
            mask |= ((unsigned)s) << u;
            mem = s ? -0.05f : mem;
        }
        g_spk[(b * 32 + tw) * 1024 + d] = mask;
    }
}

// ---------------------------------------------------------------------------
// Kernel 4: out = tanh((r*(s*ic*0.5) + (1-r)*xt) * 0.5), fully parallel
// ---------------------------------------------------------------------------
__global__ void out_kernel(const float* __restrict__ rs, float* __restrict__ out) {
    const int i = blockIdx.x * blockDim.x + threadIdx.x;  // over NELEM/4
    const int e = i * 4;
    const int d = e & 1023;
    const int t = (e >> 10) & 1023;
    const int b = e >> 20;

    const float r = 1.0f / (1.0f + expf(-rs[0]));
    const float omr = 1.0f - r;
    const float rh = r * 0.5f;

    uint4 w4 = *(const uint4*)&g_spk[(b * 32 + (t >> 5)) * 1024 + d];
    const int bit = t & 31;
    float4 ic = ((const float4*)g_ic)[i];
    float4 xt = ((const float4*)g_xt)[i];

    float4 o;
    float s0 = (float)((w4.x >> bit) & 1u);
    float s1 = (float)((w4.y >> bit) & 1u);
    float s2 = (float)((w4.z >> bit) & 1u);
    float s3 = (float)((w4.w >> bit) & 1u);
    o.x = tanhf((rh * s0 * ic.x + omr * xt.x) * 0.5f);
    o.y = tanhf((rh * s1 * ic.y + omr * xt.y) * 0.5f);
    o.z = tanhf((rh * s2 * ic.z + omr * xt.z) * 0.5f);
    o.w = tanhf((rh * s3 * ic.w + omr * xt.w) * 0.5f);
    ((float4*)out)[i] = o;
}

// ---------------------------------------------------------------------------
extern "C" void kernel_launch(void* const* d_in, const int* in_sizes, int n_in,
                              void* d_out, int out_size) {
    (void)out_size;
    const float* x = nullptr;
    const float* W = nullptr;
    const float* rs = nullptr;
    const float* nz = nullptr;
    for (int i = 0; i < n_in; i++) {
        if (in_sizes[i] == NELEM) {
            if (!x) x = (const float*)d_in[i];
            else nz = (const float*)d_in[i];
        } else if (in_sizes[i] == D_ * D_) {
            W = (const float*)d_in[i];
        } else if (in_sizes[i] == 1) {
            rs = (const float*)d_in[i];
        }
    }

    prep_x_kernel<<<(NELEM / 4) / 256, 256>>>(x);

    dim3 ggrid(D_ / 128, M_ / 128);  // (8, 128)
    gemm_tf32x3_kernel<<<ggrid, 256>>>(W);

    lif_scan_kernel<<<M_ * D_ / (T_ * 128), 128>>>(nz);

    out_kernel<<<(NELEM / 4) / 256, 256>>>(rs, (float*)d_out);
}

// round 7
// speedup vs baseline: 2.3791x; 2.3791x over previous
#include <cuda_runtime.h>
#include <cuda_fp16.h>
#include <cstdint>

#define B_ 16
#define T_ 1024
#define D_ 1024
#define M_ (B_ * T_)            // 16384
#define NELEM (B_ * T_ * D_)    // 16777216

#define WSCALE 16.0f
#define WUNSCALE 0.0625f

// ---------------------------------------------------------------------------
// Scratch (static device globals)
// ---------------------------------------------------------------------------
__device__ __half g_xh[NELEM];          // hi limb of tanh(0.5x)
__device__ __half g_xl[NELEM];          // lo limb
__device__ __half g_wh[D_ * D_];        // hi limb of W*16
__device__ __half g_wl[D_ * D_];        // lo limb
__device__ float g_ic[NELEM];           // tanh(xt @ W^T)
__device__ unsigned g_spk[NELEM / 32];  // spike bits

// ---------------------------------------------------------------------------
// Helpers
// ---------------------------------------------------------------------------
__device__ __forceinline__ uint32_t h2_as_u32(__half2 v) {
    uint32_t r;
    memcpy(&r, &v, 4);
    return r;
}
__device__ __forceinline__ uint32_t smem_u32(const void* p) {
    uint32_t a;
    asm("{ .reg .u64 t; cvta.to.shared.u64 t, %1; cvt.u32.u64 %0, t; }" : "=r"(a) : "l"(p));
    return a;
}
__device__ __forceinline__ void cpa16(uint32_t dst, const void* src) {
    asm volatile("cp.async.cg.shared.global [%0], [%1], 16;" :: "r"(dst), "l"(src));
}
#define CP_COMMIT() asm volatile("cp.async.commit_group;" ::: "memory")
#define CP_WAIT(n)  asm volatile("cp.async.wait_group %0;" :: "n"(n) : "memory")

// m16n8k16 row.col f32.f16.f16.f32 (sm_80+, family-portable)
__device__ __forceinline__ void mma16816(float* c, uint32_t a0, uint32_t a1,
                                         uint32_t a2, uint32_t a3,
                                         uint32_t b0, uint32_t b1) {
    asm volatile(
        "mma.sync.aligned.m16n8k16.row.col.f32.f16.f16.f32 "
        "{%0,%1,%2,%3}, {%4,%5,%6,%7}, {%8,%9}, {%0,%1,%2,%3};"
        : "+f"(c[0]), "+f"(c[1]), "+f"(c[2]), "+f"(c[3])
        : "r"(a0), "r"(a1), "r"(a2), "r"(a3), "r"(b0), "r"(b1));
}

__device__ __forceinline__ void split_h(float v, __half& hi, __half& lo) {
    __half h = __float2half_rn(v);
    lo = __float2half_rn(v - __half2float(h));
    hi = h;
}

// ---------------------------------------------------------------------------
// Kernel 1a: xt = tanh(0.5*x), split into fp16 hi/lo limbs
// ---------------------------------------------------------------------------
__global__ void prep_x_kernel(const float* __restrict__ x) {
    int i = blockIdx.x * blockDim.x + threadIdx.x;  // over NELEM/4
    float4 v = ((const float4*)x)[i];
    float t0 = tanhf(0.5f * v.x), t1 = tanhf(0.5f * v.y);
    float t2 = tanhf(0.5f * v.z), t3 = tanhf(0.5f * v.w);
    __half h0, h1, h2, h3, l0, l1, l2, l3;
    split_h(t0, h0, l0); split_h(t1, h1, l1);
    split_h(t2, h2, l2); split_h(t3, h3, l3);
    __half2 hv0 = __halves2half2(h0, h1), hv1 = __halves2half2(h2, h3);
    __half2 lv0 = __halves2half2(l0, l1), lv1 = __halves2half2(l2, l3);
    *(uint2*)&g_xh[i * 4] = make_uint2(h2_as_u32(hv0), h2_as_u32(hv1));
    *(uint2*)&g_xl[i * 4] = make_uint2(h2_as_u32(lv0), h2_as_u32(lv1));
}

// Kernel 1b: W*16 split into fp16 hi/lo limbs
__global__ void prep_w_kernel(const float* __restrict__ w) {
    int i = blockIdx.x * blockDim.x + threadIdx.x;  // over D*D/4
    float4 v = ((const float4*)w)[i];
    __half h0, h1, h2, h3, l0, l1, l2, l3;
    split_h(v.x * WSCALE, h0, l0); split_h(v.y * WSCALE, h1, l1);
    split_h(v.z * WSCALE, h2, l2); split_h(v.w * WSCALE, h3, l3);
    __half2 hv0 = __halves2half2(h0, h1), hv1 = __halves2half2(h2, h3);
    __half2 lv0 = __halves2half2(l0, l1), lv1 = __halves2half2(l2, l3);
    *(uint2*)&g_wh[i * 4] = make_uint2(h2_as_u32(hv0), h2_as_u32(hv1));
    *(uint2*)&g_wl[i * 4] = make_uint2(h2_as_u32(lv0), h2_as_u32(lv1));
}

// ---------------------------------------------------------------------------
// Kernel 2: ic = tanh((xh+xl) @ (wh+wl)^T / 16) via mma.sync fp16 x3.
// CTA 128x128, BK=32 halves, 8 warps (64x32 warp tile), 3-stage cp.async.
// ---------------------------------------------------------------------------
#define BKH 32                 // K per stage (halves)
#define STR 40                 // padded row stride in halves (80 bytes)
#define ARR_B (128 * STR * 2)  // bytes per operand array per stage: 10240
#define STAGE_B (4 * ARR_B)    // 40960
#define OAH 0
#define OAL ARR_B
#define OBH (2 * ARR_B)
#define OBL (3 * ARR_B)
#define NKT (D_ / BKH)         // 32

__global__ __launch_bounds__(256, 1)
void gemm_fp16x3_kernel() {
    extern __shared__ __align__(128) char dsm[];

    const int tid = threadIdx.x;
    const int wid = tid >> 5;
    const int lid = tid & 31;
    const int grp = lid >> 2;       // 0..7
    const int tig = lid & 3;        // 0..3
    const int warp_m = (wid & 1) * 64;
    const int warp_n = (wid >> 1) * 32;
    const int m0 = blockIdx.y * 128;
    const int n0 = blockIdx.x * 128;
    const uint32_t sb = smem_u32(dsm);

    float acc[4][4][4];
#pragma unroll
    for (int i = 0; i < 4; i++)
#pragma unroll
        for (int j = 0; j < 4; j++)
#pragma unroll
            for (int q = 0; q < 4; q++) acc[i][j][q] = 0.0f;

    // stage loader: per array 512 16B-chunks; 256 threads -> 2/thread/array
    auto load_stage = [&](int s, int kt) {
        const int k0 = kt * BKH;
        const uint32_t st = sb + s * STAGE_B;
#pragma unroll
        for (int t = 0; t < 2; t++) {
            int id = tid + t * 256;       // 0..511
            int r = id >> 2;              // row 0..127
            int c = id & 3;               // 16B chunk (8 halves)
            uint32_t doff = (uint32_t)(r * 80 + c * 16);
            size_t ga = (size_t)(m0 + r) * D_ + k0 + c * 8;
            size_t gb = (size_t)(n0 + r) * D_ + k0 + c * 8;
            cpa16(st + OAH + doff, g_xh + ga);
            cpa16(st + OAL + doff, g_xl + ga);
            cpa16(st + OBH + doff, g_wh + gb);
            cpa16(st + OBL + doff, g_wl + gb);
        }
    };

    load_stage(0, 0);
    CP_COMMIT();
    load_stage(1, 1);
    CP_COMMIT();

    for (int kt = 0; kt < NKT; kt++) {
        const int cur = kt - (kt / 3) * 3;   // kt % 3
        CP_WAIT(1);
        __syncthreads();
        if (kt + 2 < NKT) {
            int nxt = (kt + 2) - ((kt + 2) / 3) * 3;
            load_stage(nxt, kt + 2);
        }
        CP_COMMIT();

        const __half* Ah = (const __half*)(dsm + cur * STAGE_B + OAH);
        const __half* Al = (const __half*)(dsm + cur * STAGE_B + OAL);
        const __half* Bh = (const __half*)(dsm + cur * STAGE_B + OBH);
        const __half* Bl = (const __half*)(dsm + cur * STAGE_B + OBL);

#pragma unroll
        for (int kc = 0; kc < 2; kc++) {   // two k16 chunks
            const int kb = kc * 16 + tig * 2;
            uint32_t ah[4][4], al[4][4];
#pragma unroll
            for (int mt = 0; mt < 4; mt++) {
                int rm = warp_m + mt * 16 + grp;
                const int i00 = rm * STR + kb;
                ah[mt][0] = *(const uint32_t*)&Ah[i00];
                ah[mt][1] = *(const uint32_t*)&Ah[i00 + 8 * STR];
                ah[mt][2] = *(const uint32_t*)&Ah[i00 + 8];
                ah[mt][3] = *(const uint32_t*)&Ah[i00 + 8 * STR + 8];
                al[mt][0] = *(const uint32_t*)&Al[i00];
                al[mt][1] = *(const uint32_t*)&Al[i00 + 8 * STR];
                al[mt][2] = *(const uint32_t*)&Al[i00 + 8];
                al[mt][3] = *(const uint32_t*)&Al[i00 + 8 * STR + 8];
            }
            uint32_t bh[4][2], bl[4][2];
#pragma unroll
            for (int nt = 0; nt < 4; nt++) {
                int rn = warp_n + nt * 8 + grp;
                const int i00 = rn * STR + kb;
                bh[nt][0] = *(const uint32_t*)&Bh[i00];
                bh[nt][1] = *(const uint32_t*)&Bh[i00 + 8];
                bl[nt][0] = *(const uint32_t*)&Bl[i00];
                bl[nt][1] = *(const uint32_t*)&Bl[i00 + 8];
            }
#pragma unroll
            for (int mt = 0; mt < 4; mt++)
#pragma unroll
                for (int nt = 0; nt < 4; nt++) {
                    float* c = acc[mt][nt];
                    mma16816(c, ah[mt][0], ah[mt][1], ah[mt][2], ah[mt][3],
                             bh[nt][0], bh[nt][1]);
                    mma16816(c, ah[mt][0], ah[mt][1], ah[mt][2], ah[mt][3],
                             bl[nt][0], bl[nt][1]);
                    mma16816(c, al[mt][0], al[mt][1], al[mt][2], al[mt][3],
                             bh[nt][0], bh[nt][1]);
                }
        }
    }

    // epilogue: c0=C[g][2t], c1=C[g][2t+1], c2=C[g+8][2t], c3=C[g+8][2t+1]
#pragma unroll
    for (int mt = 0; mt < 4; mt++) {
        int rm = m0 + warp_m + mt * 16 + grp;
#pragma unroll
        for (int nt = 0; nt < 4; nt++) {
            int cn = n0 + warp_n + nt * 8 + tig * 2;
            float2 v0, v1;
            v0.x = tanhf(acc[mt][nt][0] * WUNSCALE);
            v0.y = tanhf(acc[mt][nt][1] * WUNSCALE);
            v1.x = tanhf(acc[mt][nt][2] * WUNSCALE);
            v1.y = tanhf(acc[mt][nt][3] * WUNSCALE);
            *(float2*)(g_ic + (size_t)rm * D_ + cn) = v0;
            *(float2*)(g_ic + (size_t)(rm + 8) * D_ + cn) = v1;
        }
    }
}

// ---------------------------------------------------------------------------
// Kernel 3: LIF scan -> packed spike bits. One thread per (b,d) chain.
// ---------------------------------------------------------------------------
__global__ __launch_bounds__(128)
void lif_scan_kernel(const float* __restrict__ noise) {
    const int j = blockIdx.x * blockDim.x + threadIdx.x;  // 0..16383
    const int b = j >> 10;
    const int d = j & 1023;
    const size_t base = (size_t)b * T_ * D_ + d;
    const float* icp = g_ic + base;
    const float* nzp = noise + base;

    float mem = 0.0f;
    for (int tw = 0; tw < 32; tw++) {
        float icv[32], nzv[32];
#pragma unroll
        for (int u = 0; u < 32; u++) {
            size_t idx = (size_t)(tw * 32 + u) * D_;
            icv[u] = icp[idx];
            nzv[u] = nzp[idx];
        }
        unsigned mask = 0;
#pragma unroll
        for (int u = 0; u < 32; u++) {
            mem = 0.95f * mem + icv[u] + nzv[u] * 7.5e-4f + 1e-6f;
            bool s = (mem >= 0.15f);
            mask |= ((unsigned)s) << u;
            mem = s ? -0.05f : mem;
        }
        g_spk[(b * 32 + tw) * 1024 + d] = mask;
    }
}

// ---------------------------------------------------------------------------
// Kernel 4: out = tanh((r*(s*ic*0.5) + (1-r)*xt)*0.5), xt = xh + xl
// ---------------------------------------------------------------------------
__global__ void out_kernel(const float* __restrict__ rs, float* __restrict__ out) {
    const int i = blockIdx.x * blockDim.x + threadIdx.x;  // over NELEM/4
    const int e = i * 4;
    const int d = e & 1023;
    const int t = (e >> 10) & 1023;
    const int b = e >> 20;

    const float r = 1.0f / (1.0f + expf(-rs[0]));
    const float omr = 1.0f - r;
    const float rh = r * 0.5f;

    uint4 w4 = *(const uint4*)&g_spk[(b * 32 + (t >> 5)) * 1024 + d];
    const int bit = t & 31;
    float4 ic = ((const float4*)g_ic)[i];

    uint2 hu = *(const uint2*)&g_xh[e];
    uint2 lu = *(const uint2*)&g_xl[e];
    __half2 h01 = *(__half2*)&hu.x, h23 = *(__half2*)&hu.y;
    __half2 l01 = *(__half2*)&lu.x, l23 = *(__half2*)&lu.y;
    float2 hf01 = __half22float2(h01), hf23 = __half22float2(h23);
    float2 lf01 = __half22float2(l01), lf23 = __half22float2(l23);
    float x0 = hf01.x + lf01.x, x1 = hf01.y + lf01.y;
    float x2 = hf23.x + lf23.x, x3 = hf23.y + lf23.y;

    float s0 = (float)((w4.x >> bit) & 1u);
    float s1 = (float)((w4.y >> bit) & 1u);
    float s2 = (float)((w4.z >> bit) & 1u);
    float s3 = (float)((w4.w >> bit) & 1u);

    float4 o;
    o.x = tanhf((rh * s0 * ic.x + omr * x0) * 0.5f);
    o.y = tanhf((rh * s1 * ic.y + omr * x1) * 0.5f);
    o.z = tanhf((rh * s2 * ic.z + omr * x2) * 0.5f);
    o.w = tanhf((rh * s3 * ic.w + omr * x3) * 0.5f);
    ((float4*)out)[i] = o;
}

// ---------------------------------------------------------------------------
extern "C" void kernel_launch(void* const* d_in, const int* in_sizes, int n_in,
                              void* d_out, int out_size) {
    (void)out_size;
    const float* x = nullptr;
    const float* W = nullptr;
    const float* rs = nullptr;
    const float* nz = nullptr;
    for (int i = 0; i < n_in; i++) {
        if (in_sizes[i] == NELEM) {
            if (!x) x = (const float*)d_in[i];
            else nz = (const float*)d_in[i];
        } else if (in_sizes[i] == D_ * D_) {
            W = (const float*)d_in[i];
        } else if (in_sizes[i] == 1) {
            rs = (const float*)d_in[i];
        }
    }

    cudaFuncSetAttribute(gemm_fp16x3_kernel,
                         cudaFuncAttributeMaxDynamicSharedMemorySize, 3 * STAGE_B);

    prep_w_kernel<<<(D_ * D_ / 4) / 256, 256>>>(W);
    prep_x_kernel<<<(NELEM / 4) / 256, 256>>>(x);

    dim3 ggrid(D_ / 128, M_ / 128);  // (8, 128)
    gemm_fp16x3_kernel<<<ggrid, 256, 3 * STAGE_B>>>();

    lif_scan_kernel<<<M_ * D_ / (T_ * 128), 128>>>(nz);

    out_kernel<<<(NELEM / 4) / 256, 256>>>(rs, (float*)d_out);
}

// round 8
// speedup vs baseline: 2.4944x; 1.0484x over previous
#include <cuda_runtime.h>
#include <cuda_fp16.h>
#include <cstdint>

#define B_ 16
#define T_ 1024
#define D_ 1024
#define M_ (B_ * T_)            // 16384
#define NELEM (B_ * T_ * D_)    // 16777216

#define WSCALE 16.0f
#define WUNSCALE 0.0625f

#define SEGLEN 256
#define NSEG (T_ / SEGLEN)      // 4
#define WARMUP 256

// ---------------------------------------------------------------------------
// Scratch (static device globals)
// ---------------------------------------------------------------------------
__device__ __half g_xh[NELEM];          // hi limb of tanh(0.5x)
__device__ __half g_xl[NELEM];          // lo limb
__device__ __half g_wh[D_ * D_];        // hi limb of W*16
__device__ __half g_wl[D_ * D_];        // lo limb
__device__ float g_ic[NELEM];           // tanh(xt @ W^T)

// ---------------------------------------------------------------------------
// Helpers
// ---------------------------------------------------------------------------
__device__ __forceinline__ uint32_t h2_as_u32(__half2 v) {
    uint32_t r;
    memcpy(&r, &v, 4);
    return r;
}
__device__ __forceinline__ uint32_t smem_u32(const void* p) {
    uint32_t a;
    asm("{ .reg .u64 t; cvta.to.shared.u64 t, %1; cvt.u32.u64 %0, t; }" : "=r"(a) : "l"(p));
    return a;
}
__device__ __forceinline__ void cpa16(uint32_t dst, const void* src) {
    asm volatile("cp.async.cg.shared.global [%0], [%1], 16;" :: "r"(dst), "l"(src));
}
#define CP_COMMIT() asm volatile("cp.async.commit_group;" ::: "memory")
#define CP_WAIT(n)  asm volatile("cp.async.wait_group %0;" :: "n"(n) : "memory")

// m16n8k16 row.col f32.f16.f16.f32 (sm_80+, family-portable)
__device__ __forceinline__ void mma16816(float* c, uint32_t a0, uint32_t a1,
                                         uint32_t a2, uint32_t a3,
                                         uint32_t b0, uint32_t b1) {
    asm volatile(
        "mma.sync.aligned.m16n8k16.row.col.f32.f16.f16.f32 "
        "{%0,%1,%2,%3}, {%4,%5,%6,%7}, {%8,%9}, {%0,%1,%2,%3};"
        : "+f"(c[0]), "+f"(c[1]), "+f"(c[2]), "+f"(c[3])
        : "r"(a0), "r"(a1), "r"(a2), "r"(a3), "r"(b0), "r"(b1));
}

__device__ __forceinline__ void split_h(float v, __half& hi, __half& lo) {
    __half h = __float2half_rn(v);
    lo = __float2half_rn(v - __half2float(h));
    hi = h;
}

// One LIF step; MUST be used identically in warmup and main loops so that
// overlapping timesteps produce bitwise-identical mem trajectories.
__device__ __forceinline__ float lif_step(float mem, float icv, float nzv, bool& s) {
    float add = fmaf(nzv, 7.5e-4f, icv) + 1e-6f;
    mem = fmaf(0.95f, mem, add);
    s = (mem >= 0.15f);
    return s ? -0.05f : mem;
}

// ---------------------------------------------------------------------------
// Kernel 1a: xt = tanh(0.5*x), split into fp16 hi/lo limbs
// ---------------------------------------------------------------------------
__global__ void prep_x_kernel(const float* __restrict__ x) {
    int i = blockIdx.x * blockDim.x + threadIdx.x;  // over NELEM/4
    float4 v = ((const float4*)x)[i];
    float t0 = tanhf(0.5f * v.x), t1 = tanhf(0.5f * v.y);
    float t2 = tanhf(0.5f * v.z), t3 = tanhf(0.5f * v.w);
    __half h0, h1, h2, h3, l0, l1, l2, l3;
    split_h(t0, h0, l0); split_h(t1, h1, l1);
    split_h(t2, h2, l2); split_h(t3, h3, l3);
    __half2 hv0 = __halves2half2(h0, h1), hv1 = __halves2half2(h2, h3);
    __half2 lv0 = __halves2half2(l0, l1), lv1 = __halves2half2(l2, l3);
    *(uint2*)&g_xh[i * 4] = make_uint2(h2_as_u32(hv0), h2_as_u32(hv1));
    *(uint2*)&g_xl[i * 4] = make_uint2(h2_as_u32(lv0), h2_as_u32(lv1));
}

// Kernel 1b: W*16 split into fp16 hi/lo limbs
__global__ void prep_w_kernel(const float* __restrict__ w) {
    int i = blockIdx.x * blockDim.x + threadIdx.x;  // over D*D/4
    float4 v = ((const float4*)w)[i];
    __half h0, h1, h2, h3, l0, l1, l2, l3;
    split_h(v.x * WSCALE, h0, l0); split_h(v.y * WSCALE, h1, l1);
    split_h(v.z * WSCALE, h2, l2); split_h(v.w * WSCALE, h3, l3);
    __half2 hv0 = __halves2half2(h0, h1), hv1 = __halves2half2(h2, h3);
    __half2 lv0 = __halves2half2(l0, l1), lv1 = __halves2half2(l2, l3);
    *(uint2*)&g_wh[i * 4] = make_uint2(h2_as_u32(hv0), h2_as_u32(hv1));
    *(uint2*)&g_wl[i * 4] = make_uint2(h2_as_u32(lv0), h2_as_u32(lv1));
}

// ---------------------------------------------------------------------------
// Kernel 2: ic = tanh((xh+xl) @ (wh+wl)^T / 16) via mma.sync fp16 x3.
// CTA 128x128, BK=32 halves, 8 warps (64x32 warp tile), 3-stage cp.async.
// ---------------------------------------------------------------------------
#define BKH 32                 // K per stage (halves)
#define STR 40                 // padded row stride in halves (80 bytes)
#define ARR_B (128 * STR * 2)  // bytes per operand array per stage: 10240
#define STAGE_B (4 * ARR_B)    // 40960
#define OAH 0
#define OAL ARR_B
#define OBH (2 * ARR_B)
#define OBL (3 * ARR_B)
#define NKT (D_ / BKH)         // 32

__global__ __launch_bounds__(256, 1)
void gemm_fp16x3_kernel() {
    extern __shared__ __align__(128) char dsm[];

    const int tid = threadIdx.x;
    const int wid = tid >> 5;
    const int lid = tid & 31;
    const int grp = lid >> 2;       // 0..7
    const int tig = lid & 3;        // 0..3
    const int warp_m = (wid & 1) * 64;
    const int warp_n = (wid >> 1) * 32;
    const int m0 = blockIdx.y * 128;
    const int n0 = blockIdx.x * 128;
    const uint32_t sb = smem_u32(dsm);

    float acc[4][4][4];
#pragma unroll
    for (int i = 0; i < 4; i++)
#pragma unroll
        for (int j = 0; j < 4; j++)
#pragma unroll
            for (int q = 0; q < 4; q++) acc[i][j][q] = 0.0f;

    auto load_stage = [&](int s, int kt) {
        const int k0 = kt * BKH;
        const uint32_t st = sb + s * STAGE_B;
#pragma unroll
        for (int t = 0; t < 2; t++) {
            int id = tid + t * 256;       // 0..511
            int r = id >> 2;              // row 0..127
            int c = id & 3;               // 16B chunk (8 halves)
            uint32_t doff = (uint32_t)(r * 80 + c * 16);
            size_t ga = (size_t)(m0 + r) * D_ + k0 + c * 8;
            size_t gb = (size_t)(n0 + r) * D_ + k0 + c * 8;
            cpa16(st + OAH + doff, g_xh + ga);
            cpa16(st + OAL + doff, g_xl + ga);
            cpa16(st + OBH + doff, g_wh + gb);
            cpa16(st + OBL + doff, g_wl + gb);
        }
    };

    load_stage(0, 0);
    CP_COMMIT();
    load_stage(1, 1);
    CP_COMMIT();

    for (int kt = 0; kt < NKT; kt++) {
        const int cur = kt - (kt / 3) * 3;   // kt % 3
        CP_WAIT(1);
        __syncthreads();
        if (kt + 2 < NKT) {
            int nxt = (kt + 2) - ((kt + 2) / 3) * 3;
            load_stage(nxt, kt + 2);
        }
        CP_COMMIT();

        const __half* Ah = (const __half*)(dsm + cur * STAGE_B + OAH);
        const __half* Al = (const __half*)(dsm + cur * STAGE_B + OAL);
        const __half* Bh = (const __half*)(dsm + cur * STAGE_B + OBH);
        const __half* Bl = (const __half*)(dsm + cur * STAGE_B + OBL);

#pragma unroll
        for (int kc = 0; kc < 2; kc++) {   // two k16 chunks
            const int kb = kc * 16 + tig * 2;
            uint32_t ah[4][4], al[4][4];
#pragma unroll
            for (int mt = 0; mt < 4; mt++) {
                int rm = warp_m + mt * 16 + grp;
                const int i00 = rm * STR + kb;
                ah[mt][0] = *(const uint32_t*)&Ah[i00];
                ah[mt][1] = *(const uint32_t*)&Ah[i00 + 8 * STR];
                ah[mt][2] = *(const uint32_t*)&Ah[i00 + 8];
                ah[mt][3] = *(const uint32_t*)&Ah[i00 + 8 * STR + 8];
                al[mt][0] = *(const uint32_t*)&Al[i00];
                al[mt][1] = *(const uint32_t*)&Al[i00 + 8 * STR];
                al[mt][2] = *(const uint32_t*)&Al[i00 + 8];
                al[mt][3] = *(const uint32_t*)&Al[i00 + 8 * STR + 8];
            }
            uint32_t bh[4][2], bl[4][2];
#pragma unroll
            for (int nt = 0; nt < 4; nt++) {
                int rn = warp_n + nt * 8 + grp;
                const int i00 = rn * STR + kb;
                bh[nt][0] = *(const uint32_t*)&Bh[i00];
                bh[nt][1] = *(const uint32_t*)&Bh[i00 + 8];
                bl[nt][0] = *(const uint32_t*)&Bl[i00];
                bl[nt][1] = *(const uint32_t*)&Bl[i00 + 8];
            }
#pragma unroll
            for (int mt = 0; mt < 4; mt++)
#pragma unroll
                for (int nt = 0; nt < 4; nt++) {
                    float* c = acc[mt][nt];
                    mma16816(c, ah[mt][0], ah[mt][1], ah[mt][2], ah[mt][3],
                             bh[nt][0], bh[nt][1]);
                    mma16816(c, ah[mt][0], ah[mt][1], ah[mt][2], ah[mt][3],
                             bl[nt][0], bl[nt][1]);
                    mma16816(c, al[mt][0], al[mt][1], al[mt][2], al[mt][3],
                             bh[nt][0], bh[nt][1]);
                }
        }
    }

#pragma unroll
    for (int mt = 0; mt < 4; mt++) {
        int rm = m0 + warp_m + mt * 16 + grp;
#pragma unroll
        for (int nt = 0; nt < 4; nt++) {
            int cn = n0 + warp_n + nt * 8 + tig * 2;
            float2 v0, v1;
            v0.x = tanhf(acc[mt][nt][0] * WUNSCALE);
            v0.y = tanhf(acc[mt][nt][1] * WUNSCALE);
            v1.x = tanhf(acc[mt][nt][2] * WUNSCALE);
            v1.y = tanhf(acc[mt][nt][3] * WUNSCALE);
            *(float2*)(g_ic + (size_t)rm * D_ + cn) = v0;
            *(float2*)(g_ic + (size_t)(rm + 8) * D_ + cn) = v1;
        }
    }
}

// ---------------------------------------------------------------------------
// Kernel 3: segmented LIF scan + fused output blend.
// Grid: NSEG segments x 128 chain-blocks, 128 threads. Each thread runs one
// (b,d) chain over one segment, with a WARMUP-step redundant prologue that
// reconstructs mem (error <= |mem| * 0.95^WARMUP, and exactly 0 after any
// spike in the warmup window).
// ---------------------------------------------------------------------------
__global__ __launch_bounds__(128)
void lif_fused_kernel(const float* __restrict__ noise,
                      const float* __restrict__ rs,
                      float* __restrict__ out) {
    const int seg = blockIdx.x >> 7;               // 0..NSEG-1
    const int chain = (blockIdx.x & 127) * 128 + threadIdx.x;  // 0..16383
    const int b = chain >> 10;
    const int d = chain & 1023;
    const size_t base = (size_t)b * T_ * D_ + d;
    const float* icp = g_ic + base;
    const float* nzp = noise + base;

    const float r = 1.0f / (1.0f + expf(-rs[0]));
    const float omr = 1.0f - r;
    const float rh = r * 0.5f;

    float mem = 0.0f;
    const int t0 = seg * SEGLEN;

    // ---- warmup: recompute preceding WARMUP steps from mem=0 ----
    if (seg > 0) {
        for (int tc = t0 - WARMUP; tc < t0; tc += 16) {
            float icv[16], nzv[16];
#pragma unroll
            for (int u = 0; u < 16; u++) {
                size_t idx = (size_t)(tc + u) * D_;
                icv[u] = icp[idx];
                nzv[u] = nzp[idx];
            }
#pragma unroll
            for (int u = 0; u < 16; u++) {
                bool s;
                mem = lif_step(mem, icv[u], nzv[u], s);
            }
        }
    }

    // ---- main segment: scan + output blend ----
    for (int tc = t0; tc < t0 + SEGLEN; tc += 16) {
        float icv[16], nzv[16], xtv[16];
#pragma unroll
        for (int u = 0; u < 16; u++) {
            size_t idx = (size_t)(tc + u) * D_;
            icv[u] = icp[idx];
            nzv[u] = nzp[idx];
            xtv[u] = __half2float(g_xh[base + idx]) + __half2float(g_xl[base + idx]);
        }
        unsigned smask = 0;
#pragma unroll
        for (int u = 0; u < 16; u++) {
            bool s;
            mem = lif_step(mem, icv[u], nzv[u], s);
            smask |= ((unsigned)s) << u;
        }
#pragma unroll
        for (int u = 0; u < 16; u++) {
            float sv = (float)((smask >> u) & 1u);
            float o = tanhf((rh * sv * icv[u] + omr * xtv[u]) * 0.5f);
            out[base + (size_t)(tc + u) * D_] = o;
        }
    }
}

// ---------------------------------------------------------------------------
extern "C" void kernel_launch(void* const* d_in, const int* in_sizes, int n_in,
                              void* d_out, int out_size) {
    (void)out_size;
    const float* x = nullptr;
    const float* W = nullptr;
    const float* rs = nullptr;
    const float* nz = nullptr;
    for (int i = 0; i < n_in; i++) {
        if (in_sizes[i] == NELEM) {
            if (!x) x = (const float*)d_in[i];
            else nz = (const float*)d_in[i];
        } else if (in_sizes[i] == D_ * D_) {
            W = (const float*)d_in[i];
        } else if (in_sizes[i] == 1) {
            rs = (const float*)d_in[i];
        }
    }

    cudaFuncSetAttribute(gemm_fp16x3_kernel,
                         cudaFuncAttributeMaxDynamicSharedMemorySize, 3 * STAGE_B);

    prep_w_kernel<<<(D_ * D_ / 4) / 256, 256>>>(W);
    prep_x_kernel<<<(NELEM / 4) / 256, 256>>>(x);

    dim3 ggrid(D_ / 128, M_ / 128);  // (8, 128)
    gemm_fp16x3_kernel<<<ggrid, 256, 3 * STAGE_B>>>();

    lif_fused_kernel<<<NSEG * 128, 128>>>(nz, rs, (float*)d_out);
}

// round 9
// speedup vs baseline: 2.8305x; 1.1347x over previous
#include <cuda_runtime.h>
#include <cuda_fp16.h>
#include <cstdint>

#define B_ 16
#define T_ 1024
#define D_ 1024
#define M_ (B_ * T_)            // 16384
#define NELEM (B_ * T_ * D_)    // 16777216

#define WSCALE 16.0f
#define WUNSCALE 0.0625f

#define SEGLEN 128
#define NSEG (T_ / SEGLEN)      // 8
#define WARMUP 192

// ---------------------------------------------------------------------------
// Scratch (static device globals)
// ---------------------------------------------------------------------------
__device__ __half g_xh[NELEM];          // hi limb of tanh(0.5x)
__device__ __half g_xl[NELEM];          // lo limb
__device__ __half g_wh[D_ * D_];        // hi limb of W*16
__device__ __half g_wl[D_ * D_];        // lo limb
__device__ float g_ic[NELEM];           // tanh(xt @ W^T)

// ---------------------------------------------------------------------------
// Helpers
// ---------------------------------------------------------------------------
__device__ __forceinline__ uint32_t h2_as_u32(__half2 v) {
    uint32_t r;
    memcpy(&r, &v, 4);
    return r;
}
__device__ __forceinline__ uint32_t smem_u32(const void* p) {
    uint32_t a;
    asm("{ .reg .u64 t; cvta.to.shared.u64 t, %1; cvt.u32.u64 %0, t; }" : "=r"(a) : "l"(p));
    return a;
}
__device__ __forceinline__ void cpa16(uint32_t dst, const void* src) {
    asm volatile("cp.async.cg.shared.global [%0], [%1], 16;" :: "r"(dst), "l"(src));
}
#define CP_COMMIT() asm volatile("cp.async.commit_group;" ::: "memory")
#define CP_WAIT(n)  asm volatile("cp.async.wait_group %0;" :: "n"(n) : "memory")

// ldmatrix m8n8.b16 (sm_75+, family-portable)
__device__ __forceinline__ void ldsm_x4(uint32_t& r0, uint32_t& r1, uint32_t& r2,
                                        uint32_t& r3, uint32_t addr) {
    asm volatile("ldmatrix.sync.aligned.m8n8.x4.shared.b16 {%0,%1,%2,%3}, [%4];"
                 : "=r"(r0), "=r"(r1), "=r"(r2), "=r"(r3) : "r"(addr));
}
__device__ __forceinline__ void ldsm_x2(uint32_t& r0, uint32_t& r1, uint32_t addr) {
    asm volatile("ldmatrix.sync.aligned.m8n8.x2.shared.b16 {%0,%1}, [%2];"
                 : "=r"(r0), "=r"(r1) : "r"(addr));
}

// m16n8k16 row.col f32.f16.f16.f32 (sm_80+, family-portable)
__device__ __forceinline__ void mma16816(float* c, uint32_t a0, uint32_t a1,
                                         uint32_t a2, uint32_t a3,
                                         uint32_t b0, uint32_t b1) {
    asm volatile(
        "mma.sync.aligned.m16n8k16.row.col.f32.f16.f16.f32 "
        "{%0,%1,%2,%3}, {%4,%5,%6,%7}, {%8,%9}, {%0,%1,%2,%3};"
        : "+f"(c[0]), "+f"(c[1]), "+f"(c[2]), "+f"(c[3])
        : "r"(a0), "r"(a1), "r"(a2), "r"(a3), "r"(b0), "r"(b1));
}

__device__ __forceinline__ void split_h(float v, __half& hi, __half& lo) {
    __half h = __float2half_rn(v);
    lo = __float2half_rn(v - __half2float(h));
    hi = h;
}

// One LIF step; identical in warmup and main loops -> bitwise-identical
// trajectories for overlapping timesteps.
__device__ __forceinline__ float lif_step(float mem, float icv, float nzv, bool& s) {
    float add = fmaf(nzv, 7.5e-4f, icv) + 1e-6f;
    mem = fmaf(0.95f, mem, add);
    s = (mem >= 0.15f);
    return s ? -0.05f : mem;
}

// ---------------------------------------------------------------------------
// Kernel 1a: xt = tanh(0.5*x), split into fp16 hi/lo limbs
// ---------------------------------------------------------------------------
__global__ void prep_x_kernel(const float* __restrict__ x) {
    int i = blockIdx.x * blockDim.x + threadIdx.x;  // over NELEM/4
    float4 v = ((const float4*)x)[i];
    float t0 = tanhf(0.5f * v.x), t1 = tanhf(0.5f * v.y);
    float t2 = tanhf(0.5f * v.z), t3 = tanhf(0.5f * v.w);
    __half h0, h1, h2, h3, l0, l1, l2, l3;
    split_h(t0, h0, l0); split_h(t1, h1, l1);
    split_h(t2, h2, l2); split_h(t3, h3, l3);
    __half2 hv0 = __halves2half2(h0, h1), hv1 = __halves2half2(h2, h3);
    __half2 lv0 = __halves2half2(l0, l1), lv1 = __halves2half2(l2, l3);
    *(uint2*)&g_xh[i * 4] = make_uint2(h2_as_u32(hv0), h2_as_u32(hv1));
    *(uint2*)&g_xl[i * 4] = make_uint2(h2_as_u32(lv0), h2_as_u32(lv1));
}

// Kernel 1b: W*16 split into fp16 hi/lo limbs
__global__ void prep_w_kernel(const float* __restrict__ w) {
    int i = blockIdx.x * blockDim.x + threadIdx.x;  // over D*D/4
    float4 v = ((const float4*)w)[i];
    __half h0, h1, h2, h3, l0, l1, l2, l3;
    split_h(v.x * WSCALE, h0, l0); split_h(v.y * WSCALE, h1, l1);
    split_h(v.z * WSCALE, h2, l2); split_h(v.w * WSCALE, h3, l3);
    __half2 hv0 = __halves2half2(h0, h1), hv1 = __halves2half2(h2, h3);
    __half2 lv0 = __halves2half2(l0, l1), lv1 = __halves2half2(l2, l3);
    *(uint2*)&g_wh[i * 4] = make_uint2(h2_as_u32(hv0), h2_as_u32(hv1));
    *(uint2*)&g_wl[i * 4] = make_uint2(h2_as_u32(lv0), h2_as_u32(lv1));
}

// ---------------------------------------------------------------------------
// Kernel 2: ic = tanh((xh+xl) @ (wh+wl)^T / 16) via mma.sync fp16 x3.
// CTA 128x128, BK=32 halves, 8 warps (64x32 warp tile), 3-stage cp.async,
// ldmatrix fragment loads.
// ---------------------------------------------------------------------------
#define BKH 32                 // K per stage (halves)
#define STR 40                 // padded row stride in halves (80 bytes)
#define ARR_B (128 * STR * 2)  // bytes per operand array per stage: 10240
#define STAGE_B (4 * ARR_B)    // 40960
#define OAH 0
#define OAL ARR_B
#define OBH (2 * ARR_B)
#define OBL (3 * ARR_B)
#define NKT (D_ / BKH)         // 32

__global__ __launch_bounds__(256, 1)
void gemm_fp16x3_kernel() {
    extern __shared__ __align__(128) char dsm[];

    const int tid = threadIdx.x;
    const int wid = tid >> 5;
    const int lid = tid & 31;
    const int grp = lid >> 2;       // 0..7
    const int tig = lid & 3;        // 0..3
    const int warp_m = (wid & 1) * 64;
    const int warp_n = (wid >> 1) * 32;
    const int m0 = blockIdx.y * 128;
    const int n0 = blockIdx.x * 128;
    const uint32_t sb = smem_u32(dsm);

    // ldmatrix per-lane source offsets (in halves, relative to array base)
    // A (x4): row = warp_m + mt*16 + (lid&15), kcol = (lid>>4)*8
    const int a_row = warp_m + (lid & 15);
    const int a_kof = (lid >> 4) * 8;
    // B (x2): row = warp_n + nt*8 + (lid&7), kcol = ((lid>>3)&1)*8
    const int b_row = warp_n + (lid & 7);
    const int b_kof = ((lid >> 3) & 1) * 8;

    float acc[4][4][4];
#pragma unroll
    for (int i = 0; i < 4; i++)
#pragma unroll
        for (int j = 0; j < 4; j++)
#pragma unroll
            for (int q = 0; q < 4; q++) acc[i][j][q] = 0.0f;

    auto load_stage = [&](int s, int kt) {
        const int k0 = kt * BKH;
        const uint32_t st = sb + s * STAGE_B;
#pragma unroll
        for (int t = 0; t < 2; t++) {
            int id = tid + t * 256;       // 0..511
            int r = id >> 2;              // row 0..127
            int c = id & 3;               // 16B chunk (8 halves)
            uint32_t doff = (uint32_t)(r * 80 + c * 16);
            size_t ga = (size_t)(m0 + r) * D_ + k0 + c * 8;
            size_t gb = (size_t)(n0 + r) * D_ + k0 + c * 8;
            cpa16(st + OAH + doff, g_xh + ga);
            cpa16(st + OAL + doff, g_xl + ga);
            cpa16(st + OBH + doff, g_wh + gb);
            cpa16(st + OBL + doff, g_wl + gb);
        }
    };

    load_stage(0, 0);
    CP_COMMIT();
    load_stage(1, 1);
    CP_COMMIT();

    for (int kt = 0; kt < NKT; kt++) {
        const int cur = kt - (kt / 3) * 3;   // kt % 3
        CP_WAIT(1);
        __syncthreads();
        if (kt + 2 < NKT) {
            int nxt = (kt + 2) - ((kt + 2) / 3) * 3;
            load_stage(nxt, kt + 2);
        }
        CP_COMMIT();

        const uint32_t st = sb + cur * STAGE_B;

#pragma unroll
        for (int kc = 0; kc < 2; kc++) {   // two k16 chunks
            const int kb = kc * 16;
            uint32_t ah[4][4], al[4][4];
#pragma unroll
            for (int mt = 0; mt < 4; mt++) {
                uint32_t off = (uint32_t)((a_row + mt * 16) * STR + kb + a_kof) * 2;
                ldsm_x4(ah[mt][0], ah[mt][1], ah[mt][2], ah[mt][3], st + OAH + off);
                ldsm_x4(al[mt][0], al[mt][1], al[mt][2], al[mt][3], st + OAL + off);
            }
            uint32_t bh[4][2], bl[4][2];
#pragma unroll
            for (int nt = 0; nt < 4; nt++) {
                uint32_t off = (uint32_t)((b_row + nt * 8) * STR + kb + b_kof) * 2;
                ldsm_x2(bh[nt][0], bh[nt][1], st + OBH + off);
                ldsm_x2(bl[nt][0], bl[nt][1], st + OBL + off);
            }
#pragma unroll
            for (int mt = 0; mt < 4; mt++)
#pragma unroll
                for (int nt = 0; nt < 4; nt++) {
                    float* c = acc[mt][nt];
                    mma16816(c, ah[mt][0], ah[mt][1], ah[mt][2], ah[mt][3],
                             bh[nt][0], bh[nt][1]);
                    mma16816(c, ah[mt][0], ah[mt][1], ah[mt][2], ah[mt][3],
                             bl[nt][0], bl[nt][1]);
                    mma16816(c, al[mt][0], al[mt][1], al[mt][2], al[mt][3],
                             bh[nt][0], bh[nt][1]);
                }
        }
    }

#pragma unroll
    for (int mt = 0; mt < 4; mt++) {
        int rm = m0 + warp_m + mt * 16 + grp;
#pragma unroll
        for (int nt = 0; nt < 4; nt++) {
            int cn = n0 + warp_n + nt * 8 + tig * 2;
            float2 v0, v1;
            v0.x = tanhf(acc[mt][nt][0] * WUNSCALE);
            v0.y = tanhf(acc[mt][nt][1] * WUNSCALE);
            v1.x = tanhf(acc[mt][nt][2] * WUNSCALE);
            v1.y = tanhf(acc[mt][nt][3] * WUNSCALE);
            *(float2*)(g_ic + (size_t)rm * D_ + cn) = v0;
            *(float2*)(g_ic + (size_t)(rm + 8) * D_ + cn) = v1;
        }
    }
}

// ---------------------------------------------------------------------------
// Kernel 3: segmented LIF scan + fused output blend.
// NSEG=8 segments of 128 steps; warmup = up to 192 redundant steps (clipped
// at t=0, where it becomes exact). Error bound: |mem|*0.95^192 ~ 5e-5*|mem|,
// and exactly 0 after any spike inside the warmup window.
// ---------------------------------------------------------------------------
__global__ __launch_bounds__(128)
void lif_fused_kernel(const float* __restrict__ noise,
                      const float* __restrict__ rs,
                      float* __restrict__ out) {
    const int seg = blockIdx.x >> 7;                           // 0..NSEG-1
    const int chain = (blockIdx.x & 127) * 128 + threadIdx.x;  // 0..16383
    const int b = chain >> 10;
    const int d = chain & 1023;
    const size_t base = (size_t)b * T_ * D_ + d;
    const float* icp = g_ic + base;
    const float* nzp = noise + base;

    const float r = 1.0f / (1.0f + expf(-rs[0]));
    const float omr = 1.0f - r;
    const float rh = r * 0.5f;

    float mem = 0.0f;
    const int t0 = seg * SEGLEN;
    const int tw0 = (t0 - WARMUP) > 0 ? (t0 - WARMUP) : 0;

    // ---- warmup: recompute steps [tw0, t0) from mem=0 ----
    for (int tc = tw0; tc < t0; tc += 16) {
        float icv[16], nzv[16];
#pragma unroll
        for (int u = 0; u < 16; u++) {
            size_t idx = (size_t)(tc + u) * D_;
            icv[u] = icp[idx];
            nzv[u] = nzp[idx];
        }
#pragma unroll
        for (int u = 0; u < 16; u++) {
            bool s;
            mem = lif_step(mem, icv[u], nzv[u], s);
        }
    }

    // ---- main segment: scan + output blend ----
    for (int tc = t0; tc < t0 + SEGLEN; tc += 16) {
        float icv[16], nzv[16], xtv[16];
#pragma unroll
        for (int u = 0; u < 16; u++) {
            size_t idx = (size_t)(tc + u) * D_;
            icv[u] = icp[idx];
            nzv[u] = nzp[idx];
            xtv[u] = __half2float(g_xh[base + idx]) + __half2float(g_xl[base + idx]);
        }
        unsigned smask = 0;
#pragma unroll
        for (int u = 0; u < 16; u++) {
            bool s;
            mem = lif_step(mem, icv[u], nzv[u], s);
            smask |= ((unsigned)s) << u;
        }
#pragma unroll
        for (int u = 0; u < 16; u++) {
            float sv = (float)((smask >> u) & 1u);
            float o = tanhf((rh * sv * icv[u] + omr * xtv[u]) * 0.5f);
            out[base + (size_t)(tc + u) * D_] = o;
        }
    }
}

// ---------------------------------------------------------------------------
extern "C" void kernel_launch(void* const* d_in, const int* in_sizes, int n_in,
                              void* d_out, int out_size) {
    (void)out_size;
    const float* x = nullptr;
    const float* W = nullptr;
    const float* rs = nullptr;
    const float* nz = nullptr;
    for (int i = 0; i < n_in; i++) {
        if (in_sizes[i] == NELEM) {
            if (!x) x = (const float*)d_in[i];
            else nz = (const float*)d_in[i];
        } else if (in_sizes[i] == D_ * D_) {
            W = (const float*)d_in[i];
        } else if (in_sizes[i] == 1) {
            rs = (const float*)d_in[i];
        }
    }

    cudaFuncSetAttribute(gemm_fp16x3_kernel,
                         cudaFuncAttributeMaxDynamicSharedMemorySize, 3 * STAGE_B);

    prep_w_kernel<<<(D_ * D_ / 4) / 256, 256>>>(W);
    prep_x_kernel<<<(NELEM / 4) / 256, 256>>>(x);

    dim3 ggrid(D_ / 128, M_ / 128);  // (8, 128)
    gemm_fp16x3_kernel<<<ggrid, 256, 3 * STAGE_B>>>();

    lif_fused_kernel<<<NSEG * 128, 128>>>(nz, rs, (float*)d_out);
}

// round 10
// speedup vs baseline: 2.9246x; 1.0333x over previous
#include <cuda_runtime.h>
#include <cuda_fp16.h>
#include <cstdint>

#define B_ 16
#define T_ 1024
#define D_ 1024
#define M_ (B_ * T_)            // 16384
#define NELEM (B_ * T_ * D_)    // 16777216

#define WSCALE 16.0f
#define WUNSCALE 0.0625f

#define SEGLEN 128
#define NSEG (T_ / SEGLEN)      // 8
#define WARMUP 192

// ---------------------------------------------------------------------------
// Scratch (static device globals)
// ---------------------------------------------------------------------------
__device__ __half g_xh[NELEM];          // hi limb of tanh(0.5x)
__device__ __half g_xl[NELEM];          // lo limb
__device__ __half g_wh[D_ * D_];        // hi limb of W*16
__device__ __half g_wl[D_ * D_];        // lo limb
__device__ float g_ic[NELEM];           // tanh(xt @ W^T)

// ---------------------------------------------------------------------------
// Helpers
// ---------------------------------------------------------------------------
__device__ __forceinline__ uint32_t h2_as_u32(__half2 v) {
    uint32_t r;
    memcpy(&r, &v, 4);
    return r;
}
__device__ __forceinline__ uint32_t smem_u32(const void* p) {
    uint32_t a;
    asm("{ .reg .u64 t; cvta.to.shared.u64 t, %1; cvt.u32.u64 %0, t; }" : "=r"(a) : "l"(p));
    return a;
}
__device__ __forceinline__ void cpa16(uint32_t dst, const void* src) {
    asm volatile("cp.async.cg.shared.global [%0], [%1], 16;" :: "r"(dst), "l"(src));
}
#define CP_COMMIT() asm volatile("cp.async.commit_group;" ::: "memory")
#define CP_WAIT(n)  asm volatile("cp.async.wait_group %0;" :: "n"(n) : "memory")

// ldmatrix m8n8.b16 (sm_75+, family-portable)
__device__ __forceinline__ void ldsm_x4(uint32_t& r0, uint32_t& r1, uint32_t& r2,
                                        uint32_t& r3, uint32_t addr) {
    asm volatile("ldmatrix.sync.aligned.m8n8.x4.shared.b16 {%0,%1,%2,%3}, [%4];"
                 : "=r"(r0), "=r"(r1), "=r"(r2), "=r"(r3) : "r"(addr));
}
__device__ __forceinline__ void ldsm_x2(uint32_t& r0, uint32_t& r1, uint32_t addr) {
    asm volatile("ldmatrix.sync.aligned.m8n8.x2.shared.b16 {%0,%1}, [%2];"
                 : "=r"(r0), "=r"(r1) : "r"(addr));
}

// m16n8k16 row.col f32.f16.f16.f32 (sm_80+, family-portable)
__device__ __forceinline__ void mma16816(float* c, uint32_t a0, uint32_t a1,
                                         uint32_t a2, uint32_t a3,
                                         uint32_t b0, uint32_t b1) {
    asm volatile(
        "mma.sync.aligned.m16n8k16.row.col.f32.f16.f16.f32 "
        "{%0,%1,%2,%3}, {%4,%5,%6,%7}, {%8,%9}, {%0,%1,%2,%3};"
        : "+f"(c[0]), "+f"(c[1]), "+f"(c[2]), "+f"(c[3])
        : "r"(a0), "r"(a1), "r"(a2), "r"(a3), "r"(b0), "r"(b1));
}

__device__ __forceinline__ void split_h(float v, __half& hi, __half& lo) {
    __half h = __float2half_rn(v);
    lo = __float2half_rn(v - __half2float(h));
    hi = h;
}

// One LIF step; identical in warmup and main loops -> bitwise-identical
// trajectories for overlapping timesteps.
__device__ __forceinline__ float lif_step(float mem, float icv, float nzv, bool& s) {
    float add = fmaf(nzv, 7.5e-4f, icv) + 1e-6f;
    mem = fmaf(0.95f, mem, add);
    s = (mem >= 0.15f);
    return s ? -0.05f : mem;
}

// ---------------------------------------------------------------------------
// Kernel 1a: xt = tanh(0.5*x), split into fp16 hi/lo limbs
// ---------------------------------------------------------------------------
__global__ void prep_x_kernel(const float* __restrict__ x) {
    int i = blockIdx.x * blockDim.x + threadIdx.x;  // over NELEM/4
    float4 v = ((const float4*)x)[i];
    float t0 = tanhf(0.5f * v.x), t1 = tanhf(0.5f * v.y);
    float t2 = tanhf(0.5f * v.z), t3 = tanhf(0.5f * v.w);
    __half h0, h1, h2, h3, l0, l1, l2, l3;
    split_h(t0, h0, l0); split_h(t1, h1, l1);
    split_h(t2, h2, l2); split_h(t3, h3, l3);
    __half2 hv0 = __halves2half2(h0, h1), hv1 = __halves2half2(h2, h3);
    __half2 lv0 = __halves2half2(l0, l1), lv1 = __halves2half2(l2, l3);
    *(uint2*)&g_xh[i * 4] = make_uint2(h2_as_u32(hv0), h2_as_u32(hv1));
    *(uint2*)&g_xl[i * 4] = make_uint2(h2_as_u32(lv0), h2_as_u32(lv1));
}

// Kernel 1b: W*16 split into fp16 hi/lo limbs
__global__ void prep_w_kernel(const float* __restrict__ w) {
    int i = blockIdx.x * blockDim.x + threadIdx.x;  // over D*D/4
    float4 v = ((const float4*)w)[i];
    __half h0, h1, h2, h3, l0, l1, l2, l3;
    split_h(v.x * WSCALE, h0, l0); split_h(v.y * WSCALE, h1, l1);
    split_h(v.z * WSCALE, h2, l2); split_h(v.w * WSCALE, h3, l3);
    __half2 hv0 = __halves2half2(h0, h1), hv1 = __halves2half2(h2, h3);
    __half2 lv0 = __halves2half2(l0, l1), lv1 = __halves2half2(l2, l3);
    *(uint2*)&g_wh[i * 4] = make_uint2(h2_as_u32(hv0), h2_as_u32(hv1));
    *(uint2*)&g_wl[i * 4] = make_uint2(h2_as_u32(lv0), h2_as_u32(lv1));
}

// ---------------------------------------------------------------------------
// Kernel 2: ic = tanh((xh+xl) @ (wh+wl)^T / 16) via mma.sync fp16 x3.
// CTA 128x128, BK=32 halves, 16 warps (32x32 warp tile), 3-stage cp.async,
// ldmatrix fragment loads. Per-accumulator k-order identical to R9 ->
// bitwise-identical g_ic.
// ---------------------------------------------------------------------------
#define BKH 32                 // K per stage (halves)
#define STR 40                 // padded row stride in halves (80 bytes)
#define ARR_B (128 * STR * 2)  // bytes per operand array per stage: 10240
#define STAGE_B (4 * ARR_B)    // 40960
#define OAH 0
#define OAL ARR_B
#define OBH (2 * ARR_B)
#define OBL (3 * ARR_B)
#define NKT (D_ / BKH)         // 32

__global__ __launch_bounds__(512, 1)
void gemm_fp16x3_kernel() {
    extern __shared__ __align__(128) char dsm[];

    const int tid = threadIdx.x;
    const int wid = tid >> 5;
    const int lid = tid & 31;
    const int grp = lid >> 2;       // 0..7
    const int tig = lid & 3;        // 0..3
    const int warp_m = (wid & 3) * 32;
    const int warp_n = (wid >> 2) * 32;
    const int m0 = blockIdx.y * 128;
    const int n0 = blockIdx.x * 128;
    const uint32_t sb = smem_u32(dsm);

    // ldmatrix per-lane source offsets
    const int a_row = warp_m + (lid & 15);
    const int a_kof = (lid >> 4) * 8;
    const int b_row = warp_n + (lid & 7);
    const int b_kof = ((lid >> 3) & 1) * 8;

    float acc[2][4][4];
#pragma unroll
    for (int i = 0; i < 2; i++)
#pragma unroll
        for (int j = 0; j < 4; j++)
#pragma unroll
            for (int q = 0; q < 4; q++) acc[i][j][q] = 0.0f;

    auto load_stage = [&](int s, int kt) {
        const int k0 = kt * BKH;
        const uint32_t st = sb + s * STAGE_B;
        int r = tid >> 2;             // row 0..127
        int c = tid & 3;              // 16B chunk (8 halves)
        uint32_t doff = (uint32_t)(r * 80 + c * 16);
        size_t ga = (size_t)(m0 + r) * D_ + k0 + c * 8;
        size_t gb = (size_t)(n0 + r) * D_ + k0 + c * 8;
        cpa16(st + OAH + doff, g_xh + ga);
        cpa16(st + OAL + doff, g_xl + ga);
        cpa16(st + OBH + doff, g_wh + gb);
        cpa16(st + OBL + doff, g_wl + gb);
    };

    load_stage(0, 0);
    CP_COMMIT();
    load_stage(1, 1);
    CP_COMMIT();

    for (int kt = 0; kt < NKT; kt++) {
        const int cur = kt - (kt / 3) * 3;   // kt % 3
        CP_WAIT(1);
        __syncthreads();
        if (kt + 2 < NKT) {
            int nxt = (kt + 2) - ((kt + 2) / 3) * 3;
            load_stage(nxt, kt + 2);
        }
        CP_COMMIT();

        const uint32_t st = sb + cur * STAGE_B;

#pragma unroll
        for (int kc = 0; kc < 2; kc++) {   // two k16 chunks
            const int kb = kc * 16;
            uint32_t ah[2][4], al[2][4];
#pragma unroll
            for (int mt = 0; mt < 2; mt++) {
                uint32_t off = (uint32_t)((a_row + mt * 16) * STR + kb + a_kof) * 2;
                ldsm_x4(ah[mt][0], ah[mt][1], ah[mt][2], ah[mt][3], st + OAH + off);
                ldsm_x4(al[mt][0], al[mt][1], al[mt][2], al[mt][3], st + OAL + off);
            }
            uint32_t bh[4][2], bl[4][2];
#pragma unroll
            for (int nt = 0; nt < 4; nt++) {
                uint32_t off = (uint32_t)((b_row + nt * 8) * STR + kb + b_kof) * 2;
                ldsm_x2(bh[nt][0], bh[nt][1], st + OBH + off);
                ldsm_x2(bl[nt][0], bl[nt][1], st + OBL + off);
            }
#pragma unroll
            for (int mt = 0; mt < 2; mt++)
#pragma unroll
                for (int nt = 0; nt < 4; nt++) {
                    float* c = acc[mt][nt];
                    mma16816(c, ah[mt][0], ah[mt][1], ah[mt][2], ah[mt][3],
                             bh[nt][0], bh[nt][1]);
                    mma16816(c, ah[mt][0], ah[mt][1], ah[mt][2], ah[mt][3],
                             bl[nt][0], bl[nt][1]);
                    mma16816(c, al[mt][0], al[mt][1], al[mt][2], al[mt][3],
                             bh[nt][0], bh[nt][1]);
                }
        }
    }

#pragma unroll
    for (int mt = 0; mt < 2; mt++) {
        int rm = m0 + warp_m + mt * 16 + grp;
#pragma unroll
        for (int nt = 0; nt < 4; nt++) {
            int cn = n0 + warp_n + nt * 8 + tig * 2;
            float2 v0, v1;
            v0.x = tanhf(acc[mt][nt][0] * WUNSCALE);
            v0.y = tanhf(acc[mt][nt][1] * WUNSCALE);
            v1.x = tanhf(acc[mt][nt][2] * WUNSCALE);
            v1.y = tanhf(acc[mt][nt][3] * WUNSCALE);
            *(float2*)(g_ic + (size_t)rm * D_ + cn) = v0;
            *(float2*)(g_ic + (size_t)(rm + 8) * D_ + cn) = v1;
        }
    }
}

// ---------------------------------------------------------------------------
// Kernel 3: segmented LIF scan + fused output blend.
// bid layout: seg INNERMOST -> all 8 segments of a chain block co-scheduled,
// so warmup reads of segment s hit L2 lines streamed by segment s-1's main.
// __launch_bounds__(128, 8): reg cap 64 so the 16-deep prefetch batches
// actually live in registers (R9 got squeezed to 40 regs -> low MLP).
// ---------------------------------------------------------------------------
__global__ __launch_bounds__(128, 8)
void lif_fused_kernel(const float* __restrict__ noise,
                      const float* __restrict__ rs,
                      float* __restrict__ out) {
    const int seg = blockIdx.x & (NSEG - 1);                  // 0..7
    const int chain = (blockIdx.x >> 3) * 128 + threadIdx.x;  // 0..16383
    const int b = chain >> 10;
    const int d = chain & 1023;
    const size_t base = (size_t)b * T_ * D_ + d;
    const float* icp = g_ic + base;
    const float* nzp = noise + base;

    const float r = 1.0f / (1.0f + expf(-rs[0]));
    const float omr = 1.0f - r;
    const float rh = r * 0.5f;

    float mem = 0.0f;
    const int t0 = seg * SEGLEN;
    const int tw0 = (t0 - WARMUP) > 0 ? (t0 - WARMUP) : 0;

    // ---- warmup: recompute steps [tw0, t0) from mem=0 ----
    for (int tc = tw0; tc < t0; tc += 16) {
        float icv[16], nzv[16];
#pragma unroll
        for (int u = 0; u < 16; u++) {
            size_t idx = (size_t)(tc + u) * D_;
            icv[u] = icp[idx];
            nzv[u] = nzp[idx];
        }
#pragma unroll
        for (int u = 0; u < 16; u++) {
            bool s;
            mem = lif_step(mem, icv[u], nzv[u], s);
        }
    }

    // ---- main segment: scan + output blend ----
    for (int tc = t0; tc < t0 + SEGLEN; tc += 16) {
        float icv[16], nzv[16], xtv[16];
#pragma unroll
        for (int u = 0; u < 16; u++) {
            size_t idx = (size_t)(tc + u) * D_;
            icv[u] = icp[idx];
            nzv[u] = nzp[idx];
            xtv[u] = __half2float(g_xh[base + idx]) + __half2float(g_xl[base + idx]);
        }
        unsigned smask = 0;
#pragma unroll
        for (int u = 0; u < 16; u++) {
            bool s;
            mem = lif_step(mem, icv[u], nzv[u], s);
            smask |= ((unsigned)s) << u;
        }
#pragma unroll
        for (int u = 0; u < 16; u++) {
            float sv = (float)((smask >> u) & 1u);
            float o = tanhf((rh * sv * icv[u] + omr * xtv[u]) * 0.5f);
            out[base + (size_t)(tc + u) * D_] = o;
        }
    }
}

// ---------------------------------------------------------------------------
extern "C" void kernel_launch(void* const* d_in, const int* in_sizes, int n_in,
                              void* d_out, int out_size) {
    (void)out_size;
    const float* x = nullptr;
    const float* W = nullptr;
    const float* rs = nullptr;
    const float* nz = nullptr;
    for (int i = 0; i < n_in; i++) {
        if (in_sizes[i] == NELEM) {
            if (!x) x = (const float*)d_in[i];
            else nz = (const float*)d_in[i];
        } else if (in_sizes[i] == D_ * D_) {
            W = (const float*)d_in[i];
        } else if (in_sizes[i] == 1) {
            rs = (const float*)d_in[i];
        }
    }

    cudaFuncSetAttribute(gemm_fp16x3_kernel,
                         cudaFuncAttributeMaxDynamicSharedMemorySize, 3 * STAGE_B);

    prep_w_kernel<<<(D_ * D_ / 4) / 256, 256>>>(W);
    prep_x_kernel<<<(NELEM / 4) / 256, 256>>>(x);

    dim3 ggrid(D_ / 128, M_ / 128);  // (8, 128)
    gemm_fp16x3_kernel<<<ggrid, 512, 3 * STAGE_B>>>();

    lif_fused_kernel<<<NSEG * 128, 128>>>(nz, rs, (float*)d_out);
}

// round 14
// speedup vs baseline: 3.5925x; 1.2284x over previous
#include <cuda_runtime.h>
#include <cuda_fp16.h>
#include <cstdint>

#define B_ 16
#define T_ 1024
#define D_ 1024
#define M_ (B_ * T_)            // 16384
#define NELEM (B_ * T_ * D_)    // 16777216

#define WSCALE 16.0f
#define WUNSCALE 0.0625f

#define SEGLEN 128
#define NSEG (T_ / SEGLEN)      // 8
#define WARMUP 192

#define NTILE_G 1024            // 128 m-tiles x 8 n-tiles, batch-major
#define NITEM_L 512             // 16 batches x (8 seg x 4 chain-blocks)
#define GRID_PERSIST 296        // 2 CTAs per SM x 148

// ---------------------------------------------------------------------------
// Scratch (static device globals)
// ---------------------------------------------------------------------------
__device__ __half g_xh[NELEM];
__device__ __half g_xl[NELEM];
__device__ __half g_wh[D_ * D_];
__device__ __half g_wl[D_ * D_];
__device__ float g_ic[NELEM];
__device__ int g_qg;            // GEMM tile queue head
__device__ int g_ql;            // lif item queue head
__device__ int g_done[B_];      // per-batch completed GEMM tiles (target 64)

// ---------------------------------------------------------------------------
// Helpers
// ---------------------------------------------------------------------------
__device__ __forceinline__ uint32_t h2_as_u32(__half2 v) {
    uint32_t r;
    memcpy(&r, &v, 4);
    return r;
}
__device__ __forceinline__ uint32_t smem_u32(const void* p) {
    uint32_t a;
    asm("{ .reg .u64 t; cvta.to.shared.u64 t, %1; cvt.u32.u64 %0, t; }" : "=r"(a) : "l"(p));
    return a;
}
__device__ __forceinline__ void cpa16(uint32_t dst, const void* src) {
    asm volatile("cp.async.cg.shared.global [%0], [%1], 16;" :: "r"(dst), "l"(src));
}
#define CP_COMMIT() asm volatile("cp.async.commit_group;" ::: "memory")
#define CP_WAIT(n)  asm volatile("cp.async.wait_group %0;" :: "n"(n) : "memory")

__device__ __forceinline__ void ldsm_x4(uint32_t& r0, uint32_t& r1, uint32_t& r2,
                                        uint32_t& r3, uint32_t addr) {
    asm volatile("ldmatrix.sync.aligned.m8n8.x4.shared.b16 {%0,%1,%2,%3}, [%4];"
                 : "=r"(r0), "=r"(r1), "=r"(r2), "=r"(r3) : "r"(addr));
}
__device__ __forceinline__ void ldsm_x2(uint32_t& r0, uint32_t& r1, uint32_t addr) {
    asm volatile("ldmatrix.sync.aligned.m8n8.x2.shared.b16 {%0,%1}, [%2];"
                 : "=r"(r0), "=r"(r1) : "r"(addr));
}
__device__ __forceinline__ void mma16816(float* c, uint32_t a0, uint32_t a1,
                                         uint32_t a2, uint32_t a3,
                                         uint32_t b0, uint32_t b1) {
    asm volatile(
        "mma.sync.aligned.m16n8k16.row.col.f32.f16.f16.f32 "
        "{%0,%1,%2,%3}, {%4,%5,%6,%7}, {%8,%9}, {%0,%1,%2,%3};"
        : "+f"(c[0]), "+f"(c[1]), "+f"(c[2]), "+f"(c[3])
        : "r"(a0), "r"(a1), "r"(a2), "r"(a3), "r"(b0), "r"(b1));
}
__device__ __forceinline__ void split_h(float v, __half& hi, __half& lo) {
    __half h = __float2half_rn(v);
    lo = __float2half_rn(v - __half2float(h));
    hi = h;
}
__device__ __forceinline__ float lif_step(float mem, float icv, float nzv, bool& s) {
    float add = fmaf(nzv, 7.5e-4f, icv) + 1e-6f;
    mem = fmaf(0.95f, mem, add);
    s = (mem >= 0.15f);
    return s ? -0.05f : mem;
}

// ---------------------------------------------------------------------------
// Kernel 1a: xt = tanh(0.5*x) -> fp16 hi/lo limbs
// ---------------------------------------------------------------------------
__global__ void prep_x_kernel(const float* __restrict__ x) {
    int i = blockIdx.x * blockDim.x + threadIdx.x;  // over NELEM/4
    float4 v = ((const float4*)x)[i];
    float t0 = tanhf(0.5f * v.x), t1 = tanhf(0.5f * v.y);
    float t2 = tanhf(0.5f * v.z), t3 = tanhf(0.5f * v.w);
    __half h0, h1, h2, h3, l0, l1, l2, l3;
    split_h(t0, h0, l0); split_h(t1, h1, l1);
    split_h(t2, h2, l2); split_h(t3, h3, l3);
    __half2 hv0 = __halves2half2(h0, h1), hv1 = __halves2half2(h2, h3);
    __half2 lv0 = __halves2half2(l0, l1), lv1 = __halves2half2(l2, l3);
    *(uint2*)&g_xh[i * 4] = make_uint2(h2_as_u32(hv0), h2_as_u32(hv1));
    *(uint2*)&g_xl[i * 4] = make_uint2(h2_as_u32(lv0), h2_as_u32(lv1));
}

// Kernel 1b: W*16 -> fp16 hi/lo limbs; block 0 also resets queues/flags.
__global__ void prep_w_kernel(const float* __restrict__ w) {
    if (blockIdx.x == 0 && threadIdx.x < B_ + 2) {
        if (threadIdx.x == 0) g_qg = 0;
        else if (threadIdx.x == 1) g_ql = 0;
        else g_done[threadIdx.x - 2] = 0;
    }
    int i = blockIdx.x * blockDim.x + threadIdx.x;  // over D*D/4
    float4 v = ((const float4*)w)[i];
    __half h0, h1, h2, h3, l0, l1, l2, l3;
    split_h(v.x * WSCALE, h0, l0); split_h(v.y * WSCALE, h1, l1);
    split_h(v.z * WSCALE, h2, l2); split_h(v.w * WSCALE, h3, l3);
    __half2 hv0 = __halves2half2(h0, h1), hv1 = __halves2half2(h2, h3);
    __half2 lv0 = __halves2half2(l0, l1), lv1 = __halves2half2(l2, l3);
    *(uint2*)&g_wh[i * 4] = make_uint2(h2_as_u32(hv0), h2_as_u32(hv1));
    *(uint2*)&g_wl[i * 4] = make_uint2(h2_as_u32(lv0), h2_as_u32(lv1));
}

// ---------------------------------------------------------------------------
// GEMM tile worker: 128x128 tile, BK=32, 8 warps (64x32 warp tile),
// 2-stage cp.async double buffer, ldmatrix fragments, fp16 x3 limbs.
// ---------------------------------------------------------------------------
#define BKH 32
#define STR 40
#define ARR_B (128 * STR * 2)  // 10240
#define STAGE_B (4 * ARR_B)    // 40960
#define OAH 0
#define OAL ARR_B
#define OBH (2 * ARR_B)
#define OBL (3 * ARR_B)
#define NKT (D_ / BKH)         // 32

__device__ void gemm_tile(int tile, char* dsm, int tid) {
    const int y = tile >> 3;           // m-tile 0..127
    const int xw = tile & 7;           // n-tile 0..7
    const int m0 = y * 128;
    const int n0 = xw * 128;
    const int wid = tid >> 5;
    const int lid = tid & 31;
    const int grp = lid >> 2;
    const int tig = lid & 3;
    const int warp_m = (wid & 1) * 64;
    const int warp_n = (wid >> 1) * 32;
    const uint32_t sb = smem_u32(dsm);

    const int a_row = warp_m + (lid & 15);
    const int a_kof = (lid >> 4) * 8;
    const int b_row = warp_n + (lid & 7);
    const int b_kof = ((lid >> 3) & 1) * 8;

    float acc[4][4][4];
#pragma unroll
    for (int i = 0; i < 4; i++)
#pragma unroll
        for (int j = 0; j < 4; j++)
#pragma unroll
            for (int q = 0; q < 4; q++) acc[i][j][q] = 0.0f;

    auto load_stage = [&](int s, int kt) {
        const int k0 = kt * BKH;
        const uint32_t st = sb + s * STAGE_B;
#pragma unroll
        for (int t = 0; t < 2; t++) {
            int id = tid + t * 256;
            int r = id >> 2;
            int c = id & 3;
            uint32_t doff = (uint32_t)(r * 80 + c * 16);
            size_t ga = (size_t)(m0 + r) * D_ + k0 + c * 8;
            size_t gb = (size_t)(n0 + r) * D_ + k0 + c * 8;
            cpa16(st + OAH + doff, g_xh + ga);
            cpa16(st + OAL + doff, g_xl + ga);
            cpa16(st + OBH + doff, g_wh + gb);
            cpa16(st + OBL + doff, g_wl + gb);
        }
    };

    load_stage(0, 0);
    CP_COMMIT();
    load_stage(1, 1);
    CP_COMMIT();

    for (int kt = 0; kt < NKT; kt++) {
        const int cur = kt & 1;
        CP_WAIT(1);
        __syncthreads();

        const uint32_t st = sb + cur * STAGE_B;
#pragma unroll
        for (int kc = 0; kc < 2; kc++) {
            const int kb = kc * 16;
            uint32_t ah[4][4], al[4][4];
#pragma unroll
            for (int mt = 0; mt < 4; mt++) {
                uint32_t off = (uint32_t)((a_row + mt * 16) * STR + kb + a_kof) * 2;
                ldsm_x4(ah[mt][0], ah[mt][1], ah[mt][2], ah[mt][3], st + OAH + off);
                ldsm_x4(al[mt][0], al[mt][1], al[mt][2], al[mt][3], st + OAL + off);
            }
            uint32_t bh[4][2], bl[4][2];
#pragma unroll
            for (int nt = 0; nt < 4; nt++) {
                uint32_t off = (uint32_t)((b_row + nt * 8) * STR + kb + b_kof) * 2;
                ldsm_x2(bh[nt][0], bh[nt][1], st + OBH + off);
                ldsm_x2(bl[nt][0], bl[nt][1], st + OBL + off);
            }
#pragma unroll
            for (int mt = 0; mt < 4; mt++)
#pragma unroll
                for (int nt = 0; nt < 4; nt++) {
                    float* c = acc[mt][nt];
                    mma16816(c, ah[mt][0], ah[mt][1], ah[mt][2], ah[mt][3],
                             bh[nt][0], bh[nt][1]);
                    mma16816(c, ah[mt][0], ah[mt][1], ah[mt][2], ah[mt][3],
                             bl[nt][0], bl[nt][1]);
                    mma16816(c, al[mt][0], al[mt][1], al[mt][2], al[mt][3],
                             bh[nt][0], bh[nt][1]);
                }
        }

        __syncthreads();           // all warps done reading stage cur
        if (kt + 2 < NKT) load_stage(cur, kt + 2);
        CP_COMMIT();               // empty group near the end keeps counts aligned
    }

    // epilogue
#pragma unroll
    for (int mt = 0; mt < 4; mt++) {
        int rm = m0 + warp_m + mt * 16 + grp;
#pragma unroll
        for (int nt = 0; nt < 4; nt++) {
            int cn = n0 + warp_n + nt * 8 + tig * 2;
            float2 v0, v1;
            v0.x = tanhf(acc[mt][nt][0] * WUNSCALE);
            v0.y = tanhf(acc[mt][nt][1] * WUNSCALE);
            v1.x = tanhf(acc[mt][nt][2] * WUNSCALE);
            v1.y = tanhf(acc[mt][nt][3] * WUNSCALE);
            *(float2*)(g_ic + (size_t)rm * D_ + cn) = v0;
            *(float2*)(g_ic + (size_t)(rm + 8) * D_ + cn) = v1;
        }
    }

    __threadfence();
    __syncthreads();               // also protects smem reuse by next tile
    if (tid == 0) atomicAdd(&g_done[y >> 3], 1);
}

// ---------------------------------------------------------------------------
// lif item worker: one (batch, seg, chain-block-of-256). Spins until the
// batch's 64 GEMM tiles are done. xt blend uses the fp16 hi limb.
// ---------------------------------------------------------------------------
__device__ void lif_item(int item, const float* __restrict__ noise,
                         float r, float* __restrict__ out, int tid) {
    const int batch = item >> 5;
    const int sub = item & 31;
    const int seg = sub >> 2;
    const int cb = sub & 3;
    const int chain = batch * 1024 + cb * 256 + tid;
    const int d = chain & 1023;
    const size_t base = (size_t)batch * T_ * D_ + d;

    if (tid == 0) {
        while (atomicAdd(&g_done[batch], 0) < 64) __nanosleep(256);
    }
    __syncthreads();
    __threadfence();

    const float* icp = g_ic + base;
    const float* nzp = noise + base;
    const float omr = 1.0f - r;
    const float rh = r * 0.5f;

    float mem = 0.0f;
    const int t0 = seg * SEGLEN;
    const int tw0 = (t0 - WARMUP) > 0 ? (t0 - WARMUP) : 0;

    for (int tc = tw0; tc < t0; tc += 16) {
        float icv[16], nzv[16];
#pragma unroll
        for (int u = 0; u < 16; u++) {
            size_t idx = (size_t)(tc + u) * D_;
            icv[u] = icp[idx];
            nzv[u] = nzp[idx];
        }
#pragma unroll
        for (int u = 0; u < 16; u++) {
            bool s;
            mem = lif_step(mem, icv[u], nzv[u], s);
        }
    }

    for (int tc = t0; tc < t0 + SEGLEN; tc += 16) {
        float icv[16], nzv[16], xtv[16];
#pragma unroll
        for (int u = 0; u < 16; u++) {
            size_t idx = (size_t)(tc + u) * D_;
            icv[u] = icp[idx];
            nzv[u] = nzp[idx];
            xtv[u] = __half2float(g_xh[base + idx]);
        }
        unsigned smask = 0;
#pragma unroll
        for (int u = 0; u < 16; u++) {
            bool s;
            mem = lif_step(mem, icv[u], nzv[u], s);
            smask |= ((unsigned)s) << u;
        }
#pragma unroll
        for (int u = 0; u < 16; u++) {
            float sv = (float)((smask >> u) & 1u);
            float o = tanhf((rh * sv * icv[u] + omr * xtv[u]) * 0.5f);
            out[base + (size_t)(tc + u) * D_] = o;
        }
    }
}

// ---------------------------------------------------------------------------
// Persistent mega-kernel: claim GEMM tiles, then lif items.
// Deadlock-free: lif items are claimed only after ALL gemm tiles are
// claimed; claimed tiles execute on resident CTAs, so spins always make
// progress.
// ---------------------------------------------------------------------------
__global__ __launch_bounds__(256, 2)
void mega_kernel(const float* __restrict__ noise,
                 const float* __restrict__ rs,
                 float* __restrict__ out) {
    extern __shared__ __align__(128) char dsm[];
    const int tid = threadIdx.x;
    __shared__ int s_work;

    const float r = 1.0f / (1.0f + expf(-rs[0]));

    for (;;) {
        if (tid == 0) s_work = atomicAdd(&g_qg, 1);
        __syncthreads();
        int t = s_work;
        __syncthreads();
        if (t >= NTILE_G) break;
        gemm_tile(t, dsm, tid);
    }

    for (;;) {
        if (tid == 0) s_work = atomicAdd(&g_ql, 1);
        __syncthreads();
        int l = s_work;
        __syncthreads();
        if (l >= NITEM_L) break;
        lif_item(l, noise, r, out, tid);
    }
}

// ---------------------------------------------------------------------------
extern "C" void kernel_launch(void* const* d_in, const int* in_sizes, int n_in,
                              void* d_out, int out_size) {
    (void)out_size;
    const float* x = nullptr;
    const float* W = nullptr;
    const float* rs = nullptr;
    const float* nz = nullptr;
    for (int i = 0; i < n_in; i++) {
        if (in_sizes[i] == NELEM) {
            if (!x) x = (const float*)d_in[i];
            else nz = (const float*)d_in[i];
        } else if (in_sizes[i] == D_ * D_) {
            W = (const float*)d_in[i];
        } else if (in_sizes[i] == 1) {
            rs = (const float*)d_in[i];
        }
    }

    cudaFuncSetAttribute(mega_kernel,
                         cudaFuncAttributeMaxDynamicSharedMemorySize, 2 * STAGE_B);

    prep_w_kernel<<<(D_ * D_ / 4) / 256, 256>>>(W);
    prep_x_kernel<<<(NELEM / 4) / 256, 256>>>(x);

    mega_kernel<<<GRID_PERSIST, 256, 2 * STAGE_B>>>(nz, rs, (float*)d_out);
}